// round 1
// baseline (speedup 1.0000x reference)
#include <cuda_runtime.h>
#include <cuda_bf16.h>
#include <cstdint>

// out[b,n,d] = x[b,n] * W[n,d] + bias[n,d]
// B=128, N=1024, D=512 (fp32). Pure HBM-write-bound broadcast FMA.
// Vectorized float4: D/4 = 128 float4 per (b,n) row.

static constexpr int B_ = 128;
static constexpr int N_ = 1024;
static constexpr int D_ = 512;
static constexpr int D4 = D_ / 4;                 // 128
static constexpr long long TOTAL4 = (long long)B_ * N_ * D4;  // 16,777,216

__global__ __launch_bounds__(256) void bcast_fma_kernel(
    const float* __restrict__ x,       // [B, N, 1]
    const float4* __restrict__ W4,     // [N, D/4]
    const float4* __restrict__ b4,     // [N, D/4]
    float4* __restrict__ out4)         // [B, N, D/4]
{
    // idx4 in [0, B*N*D4)
    unsigned int idx4 = blockIdx.x * blockDim.x + threadIdx.x;

    // Decompose: d4 = idx4 % 128, n = (idx4 >> 7) % 1024, b = idx4 >> 17
    unsigned int nd4 = idx4 & ((N_ * D4) - 1);   // within one batch: n*D4 + d4
    unsigned int bb  = idx4 >> 17;               // / (N*D4) = / 131072
    unsigned int n   = nd4 >> 7;                 // / D4

    float s = x[bb * N_ + n];                    // scalar broadcast (L2-resident)
    float4 w = W4[nd4];                          // W and bias are [N, D4] — nd4 indexes directly
    float4 c = b4[nd4];

    float4 o;
    o.x = fmaf(s, w.x, c.x);
    o.y = fmaf(s, w.y, c.y);
    o.z = fmaf(s, w.z, c.z);
    o.w = fmaf(s, w.w, c.w);
    out4[idx4] = o;
}

extern "C" void kernel_launch(void* const* d_in, const int* in_sizes, int n_in,
                              void* d_out, int out_size) {
    const float*  x  = (const float*)d_in[0];
    const float4* W4 = (const float4*)d_in[1];
    const float4* b4 = (const float4*)d_in[2];
    float4* out4 = (float4*)d_out;

    const int threads = 256;
    const int blocks = (int)(TOTAL4 / threads);  // 65536, exact
    bcast_fma_kernel<<<blocks, threads>>>(x, W4, b4, out4);
}

// round 2
// speedup vs baseline: 1.2322x; 1.2322x over previous
#include <cuda_runtime.h>
#include <cuda_bf16.h>
#include <cstdint>

// out[b,n,d] = x[b,n] * W[n,d] + bias[n,d]   B=128, N=1024, D=512 fp32
//
// R1 insight: flat 1-elem/thread version was LTS-bound (~14 TB/s through L2
// from redundant W/b re-reads per batch element). This version loads W/b
// ONCE per block into registers and streams 32 batch rows of stores,
// cutting L2 traffic ~64% and making the kernel a pure HBM write stream.

static constexpr int B_ = 128;
static constexpr int N_ = 1024;
static constexpr int D4 = 512 / 4;            // 128 float4 per row
static constexpr int ND4 = N_ * D4;           // 131072 float4 per batch
static constexpr int B_PER_BLK = 32;          // batch rows per block

__global__ __launch_bounds__(128) void bcast_fma_reuse_kernel(
    const float*  __restrict__ x,    // [B, N]
    const float4* __restrict__ W4,   // [N, D4]
    const float4* __restrict__ b4,   // [N, D4]
    float4*       __restrict__ out4) // [B, N, D4]
{
    const unsigned int n   = blockIdx.x;          // 0..1023
    const unsigned int tid = threadIdx.x;         // 0..127 == d4
    const unsigned int b0  = blockIdx.y * B_PER_BLK;
    const unsigned int nd4 = n * D4 + tid;

    // Weights/bias for this (n, d4): loaded once, reused 32x in registers.
    const float4 w = W4[nd4];
    const float4 c = b4[nd4];

    // Stage the 32 x-scalars for this block's batch slice in shared memory.
    __shared__ float xs[B_PER_BLK];
    if (tid < B_PER_BLK) xs[tid] = x[(b0 + tid) * N_ + n];
    __syncthreads();

    unsigned int o_idx = b0 * ND4 + nd4;
    #pragma unroll 8
    for (int i = 0; i < B_PER_BLK; ++i) {
        const float s = xs[i];
        float4 o;
        o.x = fmaf(s, w.x, c.x);
        o.y = fmaf(s, w.y, c.y);
        o.z = fmaf(s, w.z, c.z);
        o.w = fmaf(s, w.w, c.w);
        out4[o_idx] = o;
        o_idx += ND4;
    }
}

extern "C" void kernel_launch(void* const* d_in, const int* in_sizes, int n_in,
                              void* d_out, int out_size) {
    const float*  x  = (const float*)d_in[0];
    const float4* W4 = (const float4*)d_in[1];
    const float4* b4 = (const float4*)d_in[2];
    float4* out4 = (float4*)d_out;

    dim3 grid(N_, B_ / B_PER_BLK);   // 1024 x 4 = 4096 blocks
    bcast_fma_reuse_kernel<<<grid, 128>>>(x, W4, b4, out4);
}